// round 16
// baseline (speedup 1.0000x reference)
#include <cuda_runtime.h>
#include <cuda_bf16.h>
#include <cstdint>

#define DIM 256
#define NBINS 32
#define CT 32            // columns per tile
#define CSTRIDE 33       // padded column stride
#define MINW 1e-3f
#define MINH 1e-3f
#define MIND 1e-3f

// Precomputed per-(dim,bin) tables (dense in gmem)
__device__ float2 g_p0[DIM * NBINS];   // {cw_lo, 1/w}   (search table)
__device__ float4 g_pC[DIM * NBINS];   // {ch_lo, h, d0, d1}

__device__ __forceinline__ float softplus_min(float v) {
    float sp = (v > 15.f) ? v : log1pf(expf(v));
    return MIND + sp;
}

// 64 blocks x 128 threads; each warp handles one dim.
__global__ void spline_precompute_kernel(const float* __restrict__ width,
                                         const float* __restrict__ height,
                                         const float* __restrict__ deriv) {
    int d = blockIdx.x * 4 + (threadIdx.x >> 5);
    int t = threadIdx.x & 31;   // lane

    // ---- widths ----
    float wv = width[d * NBINS + t];
    float m = wv;
    #pragma unroll
    for (int o = 16; o; o >>= 1) m = fmaxf(m, __shfl_xor_sync(0xFFFFFFFFu, m, o));
    float e = __expf(wv - m);
    float s = e;
    #pragma unroll
    for (int o = 16; o; o >>= 1) s += __shfl_xor_sync(0xFFFFFFFFu, s, o);
    float sz = MINW + (1.f - NBINS * MINW) * (e / s);
    float incl = sz;
    #pragma unroll
    for (int o = 1; o < 32; o <<= 1) {
        float v = __shfl_up_sync(0xFFFFFFFFu, incl, o);
        if (t >= o) incl += v;
    }
    float cw_hi = (t == 31) ? 1.f : incl;
    float up = __shfl_up_sync(0xFFFFFFFFu, incl, 1);
    float cw_lo = (t == 0) ? 0.f : up;
    float w = cw_hi - cw_lo;

    // ---- heights ----
    float hv = height[d * NBINS + t];
    float mh = hv;
    #pragma unroll
    for (int o = 16; o; o >>= 1) mh = fmaxf(mh, __shfl_xor_sync(0xFFFFFFFFu, mh, o));
    float eh = __expf(hv - mh);
    float sh = eh;
    #pragma unroll
    for (int o = 16; o; o >>= 1) sh += __shfl_xor_sync(0xFFFFFFFFu, sh, o);
    float szh = MINH + (1.f - NBINS * MINH) * (eh / sh);
    float inclh = szh;
    #pragma unroll
    for (int o = 1; o < 32; o <<= 1) {
        float v = __shfl_up_sync(0xFFFFFFFFu, inclh, o);
        if (t >= o) inclh += v;
    }
    float ch_hi = (t == 31) ? 1.f : inclh;
    float uph = __shfl_up_sync(0xFFFFFFFFu, inclh, 1);
    float ch_lo = (t == 0) ? 0.f : uph;
    float h = ch_hi - ch_lo;

    // ---- derivatives (boundary == 1 exactly) ----
    float sp = (t < NBINS - 1) ? softplus_min(deriv[d * (NBINS - 1) + t]) : 1.f;
    float d1 = (t == NBINS - 1) ? 1.f : sp;
    float spp = __shfl_up_sync(0xFFFFFFFFu, sp, 1);
    float d0 = (t == 0) ? 1.f : spp;

    float invw = 1.f / w;

    g_p0[d * NBINS + t] = make_float2(cw_lo, invw);
    g_pC[d * NBINS + t] = make_float4(ch_lo, h, d0, d1);
}

// Main kernel: each block owns a 32-column tile.
// Search on padded 8B {cw_lo,invw}; ONE divergent correction region per k
// (common case is straight-line); then ONE LDS.128 gather of {ch_lo,h,d0,d1}.
__global__ void __launch_bounds__(256, 7)
spline_main_kernel(const float* __restrict__ x, float* __restrict__ out, int B) {
    __shared__ float2 s_p0[CT * CSTRIDE];   // ~8.25 KB {cw_lo, invw}
    __shared__ float4 s_pC[CT * CSTRIDE];   // ~16.5 KB {ch_lo, h, d0, d1}

    const int colBase = blockIdx.y * CT;
    const int tid = threadIdx.x;

    for (int i = tid; i < CT * NBINS; i += 256) {
        const int lc = i >> 5;
        const int bb = i & 31;
        const int si = lc * CSTRIDE + bb;
        s_p0[si] = g_p0[colBase * NBINS + i];
        s_pC[si] = g_pC[colBase * NBINS + i];
    }
    __syncthreads();

    const int cg   = tid & 7;     // colgroup 0..7 (4 cols each)
    const int rown = tid >> 3;    // 0..31
    const int lc0  = cg * 4;
    const int colOff = colBase + lc0;

    float* __restrict__ outY = out;
    float* __restrict__ outL = out + B * DIM;   // 16.7M < 2^31, int ok

    const int startRow = blockIdx.x * 32 + rown;
    const int stride   = gridDim.x * 32;
    int idx = startRow * DIM + colOff;
    const int idxStep = stride * DIM;

    for (int row = startRow; row < B; row += stride, idx += idxStep) {
        const float4 xv = *(const float4*)(x + idx);
        float yv[4], lv[4];
        #pragma unroll
        for (int k = 0; k < 4; k++) {
            const int lc = lc0 + k;
            const float2* __restrict__ col0 = s_p0 + lc * CSTRIDE;
            float xs = (k == 0) ? xv.x : (k == 1) ? xv.y : (k == 2) ? xv.z : xv.w;
            float xc = __saturatef(xs);

            // uniform guess; single divergent correction region
            int b = __float2int_rd(xc * 32.f);
            b = min(b, NBINS - 1);
            float2 p0 = col0[b];
            float theta = (xc - p0.x) * p0.y;
            int off = (theta >= 1.f ? 1 : 0) - (theta < 0.f ? 1 : 0);
            if (off != 0) {
                b = min(max(b + off, 0), NBINS - 1);
                p0 = col0[b];
                theta = (xc - p0.x) * p0.y;
                while ((theta < 0.f && b > 0) || (theta >= 1.f && b < NBINS - 1)) {
                    b += (theta >= 1.f) ? 1 : -1;
                    p0 = col0[b];
                    theta = (xc - p0.x) * p0.y;
                }
            }

            const float4 pc = s_pC[lc * CSTRIDE + b];

            float omt    = 1.f - theta;
            float t1m    = theta * omt;
            float th2    = theta * theta;
            float h      = pc.y;
            float delta  = h * p0.y;        // h * invw
            float delta2 = delta * delta;
            float dd0 = pc.z, dd1 = pc.w;

            float num  = h * fmaf(delta, th2, dd0 * t1m);
            float den  = fmaf(dd0 + dd1 - 2.f * delta, t1m, delta);
            float rden = __fdividef(1.f, den);
            float yin  = fmaf(num, rden, pc.x);

            float dnum = delta2 * fmaf(dd1, th2, fmaf(2.f * delta, t1m, dd0 * omt * omt));
            float lin  = __logf(dnum * rden * rden);

            bool inside = (xs >= 0.f) && (xs <= 1.f);
            yv[k] = inside ? yin : xs;
            lv[k] = inside ? lin : 0.f;
        }
        *(float4*)(outY + idx) = make_float4(yv[0], yv[1], yv[2], yv[3]);
        *(float4*)(outL + idx) = make_float4(lv[0], lv[1], lv[2], lv[3]);
    }
}

extern "C" void kernel_launch(void* const* d_in, const int* in_sizes, int n_in,
                              void* d_out, int out_size) {
    const float* x      = (const float*)d_in[0];
    const float* width  = (const float*)d_in[1];
    const float* height = (const float*)d_in[2];
    const float* deriv  = (const float*)d_in[3];
    float* out = (float*)d_out;

    const int B = in_sizes[0] / DIM;

    spline_precompute_kernel<<<DIM / 4, 128>>>(width, height, deriv);

    // 128 x-blocks: 65536/(128*32) = exactly 16 iterations per block (no straggler tail)
    dim3 grid(128, DIM / CT);
    spline_main_kernel<<<grid, 256>>>(x, out, B);
}